// round 16
// baseline (speedup 1.0000x reference)
#include <cuda_runtime.h>
#include <cuda_fp16.h>
#include <cstdint>

// ============================================================================
// CalderaLinear:  out = x @ (dequant(q) + dequant(l) @ dequant(r))^T + bias
//   1. prep (merged): dequant l -> g_lh AND dequant+transpose r -> g_rt.
//   2. GEMM_W (HMMA, K=256): W = lh @ rt^T + dequant(q), fp16 [DOUT, DIN].
//      R15: 64x128 tile, 256 thr (2Mx4N), 3-STAGE rolling pipeline (73KB
//      smem) -> 3 CTAs/SM; load/MMA/epilogue phases overlap across CTAs.
//   3. convert_x: x -> fp16 (HBM-bound, ~30us floor).
//   4. GEMM2 (HMMA, K=4096): out = xh @ W^T + bias (fp32).
//      Proven config: 128x128 tile, 8 warps (2Mx4N, warp 64x32), cp.async
//      3-stage (wait_group 1), SW128 swizzle, ldmatrix.x4 TN, 2 CTAs/SM.
// LOCKED LESSONS: no cache hints; no manual fragment ping-pong near reg cap;
// no single-producer warp specialization; GEMM2 config final (3 rewrites
// failed); warp tiles below 64x32 raise L1 reread (R9).
// ============================================================================

#define GROUPSZ 128
#define NSTAGE  3
#define BM      128
#define KCH     64   // halves per chunk = 128B per row
#define NTHR    256  // 8 warps

// ---------------- static scratch (allocation-free contract) ----------------
#define MAX_TOK  8192
#define MAX_DIN  4096
#define MAX_R    256
#define MAX_DOUT 4096

__device__ __half g_xh[(size_t)MAX_TOK  * MAX_DIN];   // [tok, DIN]
__device__ __half g_w [(size_t)MAX_DOUT * MAX_DIN];   // [out, DIN] fused W
__device__ __half g_lh[(size_t)MAX_DOUT * MAX_R];     // [out, R]
__device__ __half g_rt[(size_t)MAX_DIN  * MAX_R];     // [DIN, R] = r^T

// ---------------- PTX helpers ----------------
__device__ __forceinline__ uint32_t smem_u32(const void* p) {
    uint32_t a;
    asm("{ .reg .u64 t; cvta.to.shared.u64 t, %1; cvt.u32.u64 %0, t; }"
        : "=r"(a) : "l"(p));
    return a;
}

__device__ __forceinline__ void cp16(uint32_t dst, const void* src) {
    asm volatile("cp.async.cg.shared.global [%0], [%1], 16;" :: "r"(dst), "l"(src));
}

#define CP_COMMIT() asm volatile("cp.async.commit_group;" ::: "memory")
#define CP_WAIT1()  asm volatile("cp.async.wait_group 1;" ::: "memory")
#define CP_WAIT0()  asm volatile("cp.async.wait_group 0;" ::: "memory")

#define LDSM4(r0, r1, r2, r3, addr) \
    asm volatile("ldmatrix.sync.aligned.m8n8.x4.shared.b16 {%0,%1,%2,%3}, [%4];" \
                 : "=r"(r0), "=r"(r1), "=r"(r2), "=r"(r3) : "r"(addr))

#define MMA16816(d, a, b0, b1) \
    asm volatile("mma.sync.aligned.m16n8k16.row.col.f32.f16.f16.f32 " \
                 "{%0,%1,%2,%3},{%4,%5,%6,%7},{%8,%9},{%0,%1,%2,%3};" \
                 : "+f"((d)[0]), "+f"((d)[1]), "+f"((d)[2]), "+f"((d)[3]) \
                 : "r"((a)[0]), "r"((a)[1]), "r"((a)[2]), "r"((a)[3]), \
                   "r"(b0), "r"(b1))

// ---------------- prep kernels ----------------
__global__ void k_convert_x(const float* __restrict__ x, __half* __restrict__ xh,
                            size_t total4) {
    for (size_t i = blockIdx.x * (size_t)blockDim.x + threadIdx.x; i < total4;
         i += (size_t)gridDim.x * blockDim.x) {
        float4 v = reinterpret_cast<const float4*>(x)[i];
        __half2 a = __floats2half2_rn(v.x, v.y);
        __half2 b = __floats2half2_rn(v.z, v.w);
        uint2 u = make_uint2(*reinterpret_cast<uint32_t*>(&a),
                             *reinterpret_cast<uint32_t*>(&b));
        *reinterpret_cast<uint2*>(xh + i * 4) = u;
    }
}

// Merged prep: blocks [0, nlh) dequant l -> lh; blocks [nlh, ...) do the
// r dequant+transpose (32x32 tiles via smem).
__global__ void k_prep_lr(const int* __restrict__ lv, const float* __restrict__ ls,
                          __half* __restrict__ lh, size_t ltotal4, int lcols4,
                          int lgpr, int nlh,
                          const int* __restrict__ rv, const float* __restrict__ rs,
                          __half* __restrict__ rt, int DIN, int R, int nbx_rt) {
    if ((int)blockIdx.x < nlh) {
        for (size_t i = blockIdx.x * (size_t)blockDim.x + threadIdx.x; i < ltotal4;
             i += (size_t)nlh * blockDim.x) {
            size_t row = i / lcols4;
            int c4 = (int)(i - row * lcols4);
            int4 v = reinterpret_cast<const int4*>(lv)[i];
            float s = ls[row * (size_t)lgpr + (c4 >> 5)];
            __half2 a = __floats2half2_rn((float)v.x * s, (float)v.y * s);
            __half2 b = __floats2half2_rn((float)v.z * s, (float)v.w * s);
            uint2 u = make_uint2(*reinterpret_cast<uint32_t*>(&a),
                                 *reinterpret_cast<uint32_t*>(&b));
            *reinterpret_cast<uint2*>(lh + i * 4) = u;
        }
        return;
    }
    __shared__ __half tile[32][33];
    const int idx = blockIdx.x - nlh;
    const int i0 = (idx % nbx_rt) * 32, k0 = (idx / nbx_rt) * 32;
    const int tx = threadIdx.x & 31, ty = threadIdx.x >> 5;
    const int gpr = DIN / GROUPSZ;
#pragma unroll
    for (int kk = 0; kk < 32; kk += 8) {
        int k = k0 + ty + kk, i = i0 + tx;
        float s = rs[k * gpr + (i >> 7)];
        tile[ty + kk][tx] = __float2half_rn((float)rv[(size_t)k * DIN + i] * s);
    }
    __syncthreads();
#pragma unroll
    for (int kk = 0; kk < 32; kk += 8) {
        int i = i0 + ty + kk, k = k0 + tx;
        rt[(size_t)i * R + k] = tile[tx][ty + kk];
    }
}

// ---------------- GEMM_W: W[M,N] = A[M,256] @ B[N,256]^T + dequant(q) -------
// R15: 64x128 tile, 256 thr (2M x 4N), 3-stage rolling pipeline, 3 CTAs/SM.
__global__ void __launch_bounds__(NTHR, 3)
gemm_w(const __half* __restrict__ A, const __half* __restrict__ B,
       __half* __restrict__ W, const int* __restrict__ qv,
       const float* __restrict__ qs, int ldc) {
    constexpr int BMW = 64;
    constexpr int NCHW = 4;            // K = 256 -> 4 chunks
    constexpr int NSTW = 3;            // 3 stages
    constexpr int A_ST = BMW * 128;    // 8 KB
    constexpr int B_ST = 128 * 128;    // 16 KB

    extern __shared__ char smem_raw[];
    const uint32_t sb = (smem_u32(smem_raw) + 1023) & ~1023u;
    const uint32_t SA = sb;
    const uint32_t SB = sb + NSTW * A_ST;

    const int tid = threadIdx.x;
    const int lid = tid & 31;
    const int wid = tid >> 5;
    const int wm  = wid & 1;           // 2 M warps (32 rows each)
    const int wn  = wid >> 1;          // 4 N warps (32 cols each)
    const int m0 = blockIdx.y * BMW;
    const int n0 = blockIdx.x * 128;

    auto load_chunk = [&](int j, int st) {
        const size_t kb = (size_t)j * KCH;
        const uint32_t ab = SA + st * A_ST;
        const uint32_t bb = SB + st * B_ST;
#pragma unroll
        for (int it = 0; it < 2; ++it) {        // A: 64*8=512 segs
            int seg = tid + it * NTHR;
            int r_ = seg >> 3, c16 = seg & 7;
            uint32_t off = (uint32_t)(r_ << 7) +
                           (((uint32_t)c16 << 4) ^ (((uint32_t)(r_ & 7)) << 4));
            cp16(ab + off, A + (size_t)(m0 + r_) * 256 + kb + (c16 << 3));
        }
#pragma unroll
        for (int it = 0; it < 4; ++it) {        // B: 128*8=1024 segs
            int seg = tid + it * NTHR;
            int r_ = seg >> 3, c16 = seg & 7;
            uint32_t off = (uint32_t)(r_ << 7) +
                           (((uint32_t)c16 << 4) ^ (((uint32_t)(r_ & 7)) << 4));
            cp16(bb + off, B + (size_t)(n0 + r_) * 256 + kb + (c16 << 3));
        }
    };

    uint32_t aRowOff[2], aXor[2];
#pragma unroll
    for (int mt = 0; mt < 2; ++mt) {
        int arow = wm * 32 + mt * 16 + (lid & 15);
        aRowOff[mt] = (uint32_t)arow << 7;
        aXor[mt] = ((uint32_t)(arow & 7)) << 4;
    }
    const uint32_t aCb = ((uint32_t)(lid >> 4)) << 4;

    uint32_t bRowOff[2], bXor[2];
    const int nlocal = (lid & 7) + ((lid >> 4) << 3);
#pragma unroll
    for (int t = 0; t < 2; ++t) {
        int brow = wn * 32 + t * 16 + nlocal;
        bRowOff[t] = (uint32_t)brow << 7;
        bXor[t] = ((uint32_t)(brow & 7)) << 4;
    }
    const uint32_t bCb = ((uint32_t)((lid >> 3) & 1)) << 4;

    float acc[2][4][4];
#pragma unroll
    for (int mt = 0; mt < 2; ++mt)
#pragma unroll
        for (int t = 0; t < 4; ++t)
#pragma unroll
            for (int e = 0; e < 4; ++e) acc[mt][t][e] = 0.0f;

    // 3-stage rolling pipeline over 4 chunks
    load_chunk(0, 0); CP_COMMIT();
    load_chunk(1, 1); CP_COMMIT();

#pragma unroll
    for (int i = 0; i < NCHW; ++i) {
        CP_WAIT1();
        __syncthreads();

        const int j = i + 2;
        if (j < NCHW) load_chunk(j, j % NSTW);
        CP_COMMIT();

        const uint32_t ab = SA + (i % NSTW) * A_ST;
        const uint32_t bb = SB + (i % NSTW) * B_ST;
#pragma unroll
        for (int kk = 0; kk < 4; ++kk) {
            const uint32_t kbyte = (uint32_t)kk << 5;
            uint32_t a[2][4];
#pragma unroll
            for (int mt = 0; mt < 2; ++mt)
                LDSM4(a[mt][0], a[mt][1], a[mt][2], a[mt][3],
                      ab + aRowOff[mt] + ((kbyte + aCb) ^ aXor[mt]));
            uint32_t b[2][4];
#pragma unroll
            for (int t = 0; t < 2; ++t)
                LDSM4(b[t][0], b[t][1], b[t][2], b[t][3],
                      bb + bRowOff[t] + ((kbyte + bCb) ^ bXor[t]));
#pragma unroll
            for (int mt = 0; mt < 2; ++mt)
#pragma unroll
                for (int t = 0; t < 2; ++t) {
                    MMA16816(acc[mt][2 * t],     a[mt], b[t][0], b[t][1]);
                    MMA16816(acc[mt][2 * t + 1], a[mt], b[t][2], b[t][3]);
                }
        }
    }

    // epilogue: W = acc + dequant(q)
    const int rbase = m0 + wm * 32 + (lid >> 2);
    const int cbase = n0 + wn * 32 + (lid & 3) * 2;
    const int gpr = ldc >> 7;
#pragma unroll
    for (int t = 0; t < 4; ++t) {
        const int col = cbase + t * 8;
#pragma unroll
        for (int mt = 0; mt < 2; ++mt) {
            const int r0 = rbase + mt * 16;
#pragma unroll
            for (int rr = 0; rr < 2; ++rr) {
                const int row = r0 + rr * 8;
                int2 qvv = *reinterpret_cast<const int2*>(qv + (size_t)row * ldc + col);
                float s = qs[(size_t)row * gpr + (col >> 7)];
                __half2 h = __floats2half2_rn(
                    acc[mt][t][rr * 2 + 0] + (float)qvv.x * s,
                    acc[mt][t][rr * 2 + 1] + (float)qvv.y * s);
                *reinterpret_cast<__half2*>(W + (size_t)row * ldc + col) = h;
            }
        }
    }
}

// ---------------- GEMM2: C[M,N] = A[M,K] @ B[N,K]^T + bias (fp32) ----------
__global__ void __launch_bounds__(NTHR, 2)
gemm_hmma(const __half* __restrict__ A, const __half* __restrict__ B,
          float* __restrict__ Cout, const float* __restrict__ bias,
          int K, int lda, int ldb, int ldc) {
    constexpr int BN   = 128;
    constexpr int WN   = BN / 4;
    constexpr int NT16 = WN / 16;
    constexpr int A_ST = BM * 128;
    constexpr int B_ST = BN * 128;
    constexpr int ASEGS = BM * 8;
    constexpr int BSEGS = BN * 8;

    extern __shared__ char smem_raw[];
    const uint32_t sb = (smem_u32(smem_raw) + 1023) & ~1023u;
    const uint32_t SA = sb;
    const uint32_t SB = sb + NSTAGE * A_ST;

    const int tid = threadIdx.x;
    const int lid = tid & 31;
    const int wid = tid >> 5;
    const int wm  = wid & 1;
    const int wn  = wid >> 1;
    const int m0 = blockIdx.y * BM;
    const int n0 = blockIdx.x * BN;
    const int nch = K >> 6;

    auto load_chunk = [&](int j, int st) {
        const size_t kb = (size_t)j * KCH;
        const uint32_t ab = SA + st * A_ST;
        const uint32_t bb = SB + st * B_ST;
#pragma unroll
        for (int it = 0; it < ASEGS / NTHR; ++it) {
            int seg = tid + it * NTHR;
            int r_ = seg >> 3, c16 = seg & 7;
            uint32_t dst = ab + (uint32_t)(r_ << 7) +
                           (((uint32_t)c16 << 4) ^ (((uint32_t)(r_ & 7)) << 4));
            cp16(dst, A + (size_t)(m0 + r_) * lda + kb + (c16 << 3));
        }
#pragma unroll
        for (int it = 0; it < BSEGS / NTHR; ++it) {
            int seg = tid + it * NTHR;
            int r_ = seg >> 3, c16 = seg & 7;
            uint32_t dst = bb + (uint32_t)(r_ << 7) +
                           (((uint32_t)c16 << 4) ^ (((uint32_t)(r_ & 7)) << 4));
            cp16(dst, B + (size_t)(n0 + r_) * ldb + kb + (c16 << 3));
        }
    };

    uint32_t aRowOff[4], aXor[4];
#pragma unroll
    for (int mt = 0; mt < 4; ++mt) {
        int arow = wm * 64 + mt * 16 + (lid & 15);
        aRowOff[mt] = (uint32_t)arow << 7;
        aXor[mt] = ((uint32_t)(arow & 7)) << 4;
    }
    const uint32_t aCb = ((uint32_t)(lid >> 4)) << 4;

    uint32_t bRowOff[NT16], bXor[NT16];
    const int nlocal = (lid & 7) + ((lid >> 4) << 3);
#pragma unroll
    for (int t = 0; t < NT16; ++t) {
        int brow = wn * WN + t * 16 + nlocal;
        bRowOff[t] = (uint32_t)brow << 7;
        bXor[t] = ((uint32_t)(brow & 7)) << 4;
    }
    const uint32_t bCb = ((uint32_t)((lid >> 3) & 1)) << 4;

    float acc[4][4][4];
#pragma unroll
    for (int mt = 0; mt < 4; ++mt)
#pragma unroll
        for (int t = 0; t < 4; ++t)
#pragma unroll
            for (int e = 0; e < 4; ++e) acc[mt][t][e] = 0.0f;

    load_chunk(0, 0); CP_COMMIT();
    load_chunk(1, 1); CP_COMMIT();

    int st_i = 0, st_j = 2;
    for (int i = 0; i < nch; ++i) {
        CP_WAIT1();
        __syncthreads();

        int j = i + 2;
        if (j < nch) load_chunk(j, st_j);
        CP_COMMIT();

        const uint32_t ab = SA + st_i * A_ST;
        const uint32_t bb = SB + st_i * B_ST;
        if (++st_i == NSTAGE) st_i = 0;
        if (++st_j == NSTAGE) st_j = 0;

#pragma unroll
        for (int kk = 0; kk < 4; ++kk) {
            const uint32_t kbyte = (uint32_t)kk << 5;
            uint32_t a[4][4];
#pragma unroll
            for (int mt = 0; mt < 4; ++mt)
                LDSM4(a[mt][0], a[mt][1], a[mt][2], a[mt][3],
                      ab + aRowOff[mt] + ((kbyte + aCb) ^ aXor[mt]));
            uint32_t b[NT16][4];
#pragma unroll
            for (int t = 0; t < NT16; ++t)
                LDSM4(b[t][0], b[t][1], b[t][2], b[t][3],
                      bb + bRowOff[t] + ((kbyte + bCb) ^ bXor[t]));
#pragma unroll
            for (int mt = 0; mt < 4; ++mt)
#pragma unroll
                for (int t = 0; t < NT16; ++t) {
                    MMA16816(acc[mt][2 * t],     a[mt], b[t][0], b[t][1]);
                    MMA16816(acc[mt][2 * t + 1], a[mt], b[t][2], b[t][3]);
                }
        }
    }

    const int rbase = m0 + wm * 64 + (lid >> 2);
    const int cbase = n0 + wn * WN + (lid & 3) * 2;
#pragma unroll
    for (int t = 0; t < 4; ++t) {
        const int col = cbase + t * 8;
        float2 bv = *reinterpret_cast<const float2*>(bias + col);
#pragma unroll
        for (int mt = 0; mt < 4; ++mt) {
            const int r0 = rbase + mt * 16;
            float2 v0 = make_float2(acc[mt][t][0] + bv.x, acc[mt][t][1] + bv.y);
            float2 v1 = make_float2(acc[mt][t][2] + bv.x, acc[mt][t][3] + bv.y);
            *reinterpret_cast<float2*>(Cout + (size_t)r0 * ldc + col) = v0;
            *reinterpret_cast<float2*>(Cout + (size_t)(r0 + 8) * ldc + col) = v1;
        }
    }
}

// ---------------- host launch ----------------
extern "C" void kernel_launch(void* const* d_in, const int* in_sizes, int n_in,
                              void* d_out, int out_size) {
    const float* x    = (const float*)d_in[0];
    const int*   qv   = (const int*)  d_in[1];
    const float* qs   = (const float*)d_in[2];
    const int*   lv   = (const int*)  d_in[3];
    const float* ls   = (const float*)d_in[4];
    const int*   rv   = (const int*)  d_in[5];
    const float* rs   = (const float*)d_in[6];
    const float* bias = (const float*)d_in[7];

    const int DOUT = in_sizes[7];
    const int R    = in_sizes[3] / DOUT;
    const int DIN  = in_sizes[5] / R;
    const int NTOK = in_sizes[0] / DIN;

    __half *xh, *wf, *lh, *rt;
    { void* p; cudaGetSymbolAddress(&p, g_xh); xh = (__half*)p; }
    { void* p; cudaGetSymbolAddress(&p, g_w);  wf = (__half*)p; }
    { void* p; cudaGetSymbolAddress(&p, g_lh); lh = (__half*)p; }
    { void* p; cudaGetSymbolAddress(&p, g_rt); rt = (__half*)p; }

    const int SMEM  = NSTAGE * (BM * 128 + 128 * 128) + 1024;  // GEMM2 97K
    const int SMEMW = 3 * (64 * 128 + 128 * 128) + 1024;       // GEMM_W 73K
    cudaFuncSetAttribute(gemm_hmma,
                         cudaFuncAttributeMaxDynamicSharedMemorySize, SMEM);
    cudaFuncSetAttribute(gemm_w,
                         cudaFuncAttributeMaxDynamicSharedMemorySize, SMEMW);

    // 1) merged prep: l dequant (blocks 0..511) + r dequant-transpose
    const int nbx_rt = DIN / 32;                   // 128
    const int nrt = nbx_rt * (R / 32);             // 1024 transpose tiles
    k_prep_lr<<<512 + nrt, NTHR>>>(
        lv, ls, lh, (size_t)DOUT * R / 4, R / 4, R / GROUPSZ, 512,
        rv, rs, rt, DIN, R, nbx_rt);

    // 2) GEMM_W: W[DOUT, DIN] = lh @ rt^T + dequant(q)   (3 CTAs/SM)
    gemm_w<<<dim3(DIN / 128, DOUT / 64), NTHR, SMEMW>>>(lh, rt, wf, qv, qs, DIN);

    // 3) x -> fp16
    k_convert_x<<<2960, NTHR>>>(x, xh, (size_t)NTOK * DIN / 4);

    // 4) GEMM2: out = xh @ W^T + bias   (fp32, K=4096)
    gemm_hmma<<<dim3(DOUT / 128, NTOK / BM), NTHR, SMEM>>>(
        xh, wf, (float*)d_out, bias, DIN, DIN, DIN, DOUT);
}

// round 17
// speedup vs baseline: 1.0107x; 1.0107x over previous
#include <cuda_runtime.h>
#include <cuda_fp16.h>
#include <cstdint>

// ============================================================================
// CalderaLinear:  out = x @ (dequant(q) + dequant(l) @ dequant(r))^T + bias
//   1. prep (merged): dequant l -> g_lh AND dequant+transpose r -> g_rt
//      in ONE launch (block-role split).
//   2. GEMM_W (HMMA, K=256): W = lh @ rt^T + dequant(q), fp16 [DOUT, DIN].
//      Proven optimum: 64x128 tile, 256 thr (2Mx4N), FULL-K preload
//      (96KB smem), one wait, 2 CTAs/SM.
//   3. convert_x: x -> fp16 (HBM-bound, ~30us floor).
//   4. GEMM2 (HMMA, K=4096): out = xh @ W^T + bias (fp32).
//      Proven optimum: 128x128 tile, 8 warps (2Mx4N, warp 64x32), cp.async
//      3-stage (wait_group 1), SW128 swizzle, ldmatrix.x4 TN, 2 CTAs/SM.
// LOCKED LESSONS (all measured): no cache hints (__ldcs/__stcs regress);
// no manual fragment ping-pong near the reg cap (spills); no single-producer
// warp specialization (supply starvation); no 3-CTA pipelined GEMM_W (smem
// port contention); warp tiles below 64x32 raise L1 reread; role fusion and
// launch-order shuffles are neutral. This file == the 667.0us fixed point.
// ============================================================================

#define GROUPSZ 128
#define NSTAGE  3
#define BM      128
#define KCH     64   // halves per chunk = 128B per row
#define NTHR    256  // 8 warps

// ---------------- static scratch (allocation-free contract) ----------------
#define MAX_TOK  8192
#define MAX_DIN  4096
#define MAX_R    256
#define MAX_DOUT 4096

__device__ __half g_xh[(size_t)MAX_TOK  * MAX_DIN];   // [tok, DIN]
__device__ __half g_w [(size_t)MAX_DOUT * MAX_DIN];   // [out, DIN] fused W
__device__ __half g_lh[(size_t)MAX_DOUT * MAX_R];     // [out, R]
__device__ __half g_rt[(size_t)MAX_DIN  * MAX_R];     // [DIN, R] = r^T

// ---------------- PTX helpers ----------------
__device__ __forceinline__ uint32_t smem_u32(const void* p) {
    uint32_t a;
    asm("{ .reg .u64 t; cvta.to.shared.u64 t, %1; cvt.u32.u64 %0, t; }"
        : "=r"(a) : "l"(p));
    return a;
}

__device__ __forceinline__ void cp16(uint32_t dst, const void* src) {
    asm volatile("cp.async.cg.shared.global [%0], [%1], 16;" :: "r"(dst), "l"(src));
}

#define CP_COMMIT() asm volatile("cp.async.commit_group;" ::: "memory")
#define CP_WAIT1()  asm volatile("cp.async.wait_group 1;" ::: "memory")
#define CP_WAIT0()  asm volatile("cp.async.wait_group 0;" ::: "memory")

#define LDSM4(r0, r1, r2, r3, addr) \
    asm volatile("ldmatrix.sync.aligned.m8n8.x4.shared.b16 {%0,%1,%2,%3}, [%4];" \
                 : "=r"(r0), "=r"(r1), "=r"(r2), "=r"(r3) : "r"(addr))

#define MMA16816(d, a, b0, b1) \
    asm volatile("mma.sync.aligned.m16n8k16.row.col.f32.f16.f16.f32 " \
                 "{%0,%1,%2,%3},{%4,%5,%6,%7},{%8,%9},{%0,%1,%2,%3};" \
                 : "+f"((d)[0]), "+f"((d)[1]), "+f"((d)[2]), "+f"((d)[3]) \
                 : "r"((a)[0]), "r"((a)[1]), "r"((a)[2]), "r"((a)[3]), \
                   "r"(b0), "r"(b1))

// ---------------- prep kernels ----------------
__global__ void k_convert_x(const float* __restrict__ x, __half* __restrict__ xh,
                            size_t total4) {
    for (size_t i = blockIdx.x * (size_t)blockDim.x + threadIdx.x; i < total4;
         i += (size_t)gridDim.x * blockDim.x) {
        float4 v = reinterpret_cast<const float4*>(x)[i];
        __half2 a = __floats2half2_rn(v.x, v.y);
        __half2 b = __floats2half2_rn(v.z, v.w);
        uint2 u = make_uint2(*reinterpret_cast<uint32_t*>(&a),
                             *reinterpret_cast<uint32_t*>(&b));
        *reinterpret_cast<uint2*>(xh + i * 4) = u;
    }
}

// Merged prep: blocks [0, nlh) dequant l -> lh; blocks [nlh, ...) do the
// r dequant+transpose (32x32 tiles via smem).
__global__ void k_prep_lr(const int* __restrict__ lv, const float* __restrict__ ls,
                          __half* __restrict__ lh, size_t ltotal4, int lcols4,
                          int lgpr, int nlh,
                          const int* __restrict__ rv, const float* __restrict__ rs,
                          __half* __restrict__ rt, int DIN, int R, int nbx_rt) {
    if ((int)blockIdx.x < nlh) {
        for (size_t i = blockIdx.x * (size_t)blockDim.x + threadIdx.x; i < ltotal4;
             i += (size_t)nlh * blockDim.x) {
            size_t row = i / lcols4;
            int c4 = (int)(i - row * lcols4);
            int4 v = reinterpret_cast<const int4*>(lv)[i];
            float s = ls[row * (size_t)lgpr + (c4 >> 5)];
            __half2 a = __floats2half2_rn((float)v.x * s, (float)v.y * s);
            __half2 b = __floats2half2_rn((float)v.z * s, (float)v.w * s);
            uint2 u = make_uint2(*reinterpret_cast<uint32_t*>(&a),
                                 *reinterpret_cast<uint32_t*>(&b));
            *reinterpret_cast<uint2*>(lh + i * 4) = u;
        }
        return;
    }
    __shared__ __half tile[32][33];
    const int idx = blockIdx.x - nlh;
    const int i0 = (idx % nbx_rt) * 32, k0 = (idx / nbx_rt) * 32;
    const int tx = threadIdx.x & 31, ty = threadIdx.x >> 5;
    const int gpr = DIN / GROUPSZ;
#pragma unroll
    for (int kk = 0; kk < 32; kk += 8) {
        int k = k0 + ty + kk, i = i0 + tx;
        float s = rs[k * gpr + (i >> 7)];
        tile[ty + kk][tx] = __float2half_rn((float)rv[(size_t)k * DIN + i] * s);
    }
    __syncthreads();
#pragma unroll
    for (int kk = 0; kk < 32; kk += 8) {
        int i = i0 + ty + kk, k = k0 + tx;
        rt[(size_t)i * R + k] = tile[tx][ty + kk];
    }
}

// ---------------- GEMM_W: W[M,N] = A[M,256] @ B[N,256]^T + dequant(q) -------
// Proven optimum: 64x128 tile, 256 thr (2M x 4N), full-K preload, 2 CTAs/SM.
__global__ void __launch_bounds__(NTHR, 2)
gemm_w(const __half* __restrict__ A, const __half* __restrict__ B,
       __half* __restrict__ W, const int* __restrict__ qv,
       const float* __restrict__ qs, int ldc) {
    constexpr int BMW = 64;
    constexpr int NCH = 4;             // K = 256
    constexpr int A_ST = BMW * 128;    // 8 KB
    constexpr int B_ST = 128 * 128;    // 16 KB

    extern __shared__ char smem_raw[];
    const uint32_t sb = (smem_u32(smem_raw) + 1023) & ~1023u;
    const uint32_t SA = sb;
    const uint32_t SB = sb + NCH * A_ST;

    const int tid = threadIdx.x;
    const int lid = tid & 31;
    const int wid = tid >> 5;
    const int wm  = wid & 1;           // 2 M warps (32 rows each)
    const int wn  = wid >> 1;          // 4 N warps (32 cols each)
    const int m0 = blockIdx.y * BMW;
    const int n0 = blockIdx.x * 128;

    // preload all of K
#pragma unroll
    for (int j = 0; j < NCH; ++j) {
        const size_t kb = (size_t)j * KCH;
#pragma unroll
        for (int it = 0; it < 2; ++it) {        // A: 64*8=512 segs
            int seg = tid + it * NTHR;
            int r_ = seg >> 3, c16 = seg & 7;
            uint32_t off = (uint32_t)(r_ << 7) +
                           (((uint32_t)c16 << 4) ^ (((uint32_t)(r_ & 7)) << 4));
            cp16(SA + j * A_ST + off, A + (size_t)(m0 + r_) * 256 + kb + (c16 << 3));
        }
#pragma unroll
        for (int it = 0; it < 4; ++it) {        // B: 128*8=1024 segs
            int seg = tid + it * NTHR;
            int r_ = seg >> 3, c16 = seg & 7;
            uint32_t off = (uint32_t)(r_ << 7) +
                           (((uint32_t)c16 << 4) ^ (((uint32_t)(r_ & 7)) << 4));
            cp16(SB + j * B_ST + off, B + (size_t)(n0 + r_) * 256 + kb + (c16 << 3));
        }
    }
    CP_COMMIT();

    uint32_t aRowOff[2], aXor[2];
#pragma unroll
    for (int mt = 0; mt < 2; ++mt) {
        int arow = wm * 32 + mt * 16 + (lid & 15);
        aRowOff[mt] = (uint32_t)arow << 7;
        aXor[mt] = ((uint32_t)(arow & 7)) << 4;
    }
    const uint32_t aCb = ((uint32_t)(lid >> 4)) << 4;

    uint32_t bRowOff[2], bXor[2];
    const int nlocal = (lid & 7) + ((lid >> 4) << 3);
#pragma unroll
    for (int t = 0; t < 2; ++t) {
        int brow = wn * 32 + t * 16 + nlocal;
        bRowOff[t] = (uint32_t)brow << 7;
        bXor[t] = ((uint32_t)(brow & 7)) << 4;
    }
    const uint32_t bCb = ((uint32_t)((lid >> 3) & 1)) << 4;

    float acc[2][4][4];
#pragma unroll
    for (int mt = 0; mt < 2; ++mt)
#pragma unroll
        for (int t = 0; t < 4; ++t)
#pragma unroll
            for (int e = 0; e < 4; ++e) acc[mt][t][e] = 0.0f;

    CP_WAIT0();
    __syncthreads();

    // 16 straight k16-steps
#pragma unroll
    for (int ks = 0; ks < 16; ++ks) {
        const uint32_t ab = SA + (ks >> 2) * A_ST;
        const uint32_t bb = SB + (ks >> 2) * B_ST;
        const uint32_t kbyte = (uint32_t)(ks & 3) << 5;
        uint32_t a[2][4];
#pragma unroll
        for (int mt = 0; mt < 2; ++mt)
            LDSM4(a[mt][0], a[mt][1], a[mt][2], a[mt][3],
                  ab + aRowOff[mt] + ((kbyte + aCb) ^ aXor[mt]));
        uint32_t b[2][4];
#pragma unroll
        for (int t = 0; t < 2; ++t)
            LDSM4(b[t][0], b[t][1], b[t][2], b[t][3],
                  bb + bRowOff[t] + ((kbyte + bCb) ^ bXor[t]));
#pragma unroll
        for (int mt = 0; mt < 2; ++mt)
#pragma unroll
            for (int t = 0; t < 2; ++t) {
                MMA16816(acc[mt][2 * t],     a[mt], b[t][0], b[t][1]);
                MMA16816(acc[mt][2 * t + 1], a[mt], b[t][2], b[t][3]);
            }
    }

    // epilogue: W = acc + dequant(q)
    const int rbase = m0 + wm * 32 + (lid >> 2);
    const int cbase = n0 + wn * 32 + (lid & 3) * 2;
    const int gpr = ldc >> 7;
#pragma unroll
    for (int t = 0; t < 4; ++t) {
        const int col = cbase + t * 8;
#pragma unroll
        for (int mt = 0; mt < 2; ++mt) {
            const int r0 = rbase + mt * 16;
#pragma unroll
            for (int rr = 0; rr < 2; ++rr) {
                const int row = r0 + rr * 8;
                int2 qvv = *reinterpret_cast<const int2*>(qv + (size_t)row * ldc + col);
                float s = qs[(size_t)row * gpr + (col >> 7)];
                __half2 h = __floats2half2_rn(
                    acc[mt][t][rr * 2 + 0] + (float)qvv.x * s,
                    acc[mt][t][rr * 2 + 1] + (float)qvv.y * s);
                *reinterpret_cast<__half2*>(W + (size_t)row * ldc + col) = h;
            }
        }
    }
}

// ---------------- GEMM2: C[M,N] = A[M,K] @ B[N,K]^T + bias (fp32) ----------
__global__ void __launch_bounds__(NTHR, 2)
gemm_hmma(const __half* __restrict__ A, const __half* __restrict__ B,
          float* __restrict__ Cout, const float* __restrict__ bias,
          int K, int lda, int ldb, int ldc) {
    constexpr int BN   = 128;
    constexpr int WN   = BN / 4;
    constexpr int NT16 = WN / 16;
    constexpr int A_ST = BM * 128;
    constexpr int B_ST = BN * 128;
    constexpr int ASEGS = BM * 8;
    constexpr int BSEGS = BN * 8;

    extern __shared__ char smem_raw[];
    const uint32_t sb = (smem_u32(smem_raw) + 1023) & ~1023u;
    const uint32_t SA = sb;
    const uint32_t SB = sb + NSTAGE * A_ST;

    const int tid = threadIdx.x;
    const int lid = tid & 31;
    const int wid = tid >> 5;
    const int wm  = wid & 1;
    const int wn  = wid >> 1;
    const int m0 = blockIdx.y * BM;
    const int n0 = blockIdx.x * BN;
    const int nch = K >> 6;

    auto load_chunk = [&](int j, int st) {
        const size_t kb = (size_t)j * KCH;
        const uint32_t ab = SA + st * A_ST;
        const uint32_t bb = SB + st * B_ST;
#pragma unroll
        for (int it = 0; it < ASEGS / NTHR; ++it) {
            int seg = tid + it * NTHR;
            int r_ = seg >> 3, c16 = seg & 7;
            uint32_t dst = ab + (uint32_t)(r_ << 7) +
                           (((uint32_t)c16 << 4) ^ (((uint32_t)(r_ & 7)) << 4));
            cp16(dst, A + (size_t)(m0 + r_) * lda + kb + (c16 << 3));
        }
#pragma unroll
        for (int it = 0; it < BSEGS / NTHR; ++it) {
            int seg = tid + it * NTHR;
            int r_ = seg >> 3, c16 = seg & 7;
            uint32_t dst = bb + (uint32_t)(r_ << 7) +
                           (((uint32_t)c16 << 4) ^ (((uint32_t)(r_ & 7)) << 4));
            cp16(dst, B + (size_t)(n0 + r_) * ldb + kb + (c16 << 3));
        }
    };

    uint32_t aRowOff[4], aXor[4];
#pragma unroll
    for (int mt = 0; mt < 4; ++mt) {
        int arow = wm * 64 + mt * 16 + (lid & 15);
        aRowOff[mt] = (uint32_t)arow << 7;
        aXor[mt] = ((uint32_t)(arow & 7)) << 4;
    }
    const uint32_t aCb = ((uint32_t)(lid >> 4)) << 4;

    uint32_t bRowOff[NT16], bXor[NT16];
    const int nlocal = (lid & 7) + ((lid >> 4) << 3);
#pragma unroll
    for (int t = 0; t < NT16; ++t) {
        int brow = wn * WN + t * 16 + nlocal;
        bRowOff[t] = (uint32_t)brow << 7;
        bXor[t] = ((uint32_t)(brow & 7)) << 4;
    }
    const uint32_t bCb = ((uint32_t)((lid >> 3) & 1)) << 4;

    float acc[4][4][4];
#pragma unroll
    for (int mt = 0; mt < 4; ++mt)
#pragma unroll
        for (int t = 0; t < 4; ++t)
#pragma unroll
            for (int e = 0; e < 4; ++e) acc[mt][t][e] = 0.0f;

    load_chunk(0, 0); CP_COMMIT();
    load_chunk(1, 1); CP_COMMIT();

    int st_i = 0, st_j = 2;
    for (int i = 0; i < nch; ++i) {
        CP_WAIT1();
        __syncthreads();

        int j = i + 2;
        if (j < nch) load_chunk(j, st_j);
        CP_COMMIT();

        const uint32_t ab = SA + st_i * A_ST;
        const uint32_t bb = SB + st_i * B_ST;
        if (++st_i == NSTAGE) st_i = 0;
        if (++st_j == NSTAGE) st_j = 0;

#pragma unroll
        for (int kk = 0; kk < 4; ++kk) {
            const uint32_t kbyte = (uint32_t)kk << 5;
            uint32_t a[4][4];
#pragma unroll
            for (int mt = 0; mt < 4; ++mt)
                LDSM4(a[mt][0], a[mt][1], a[mt][2], a[mt][3],
                      ab + aRowOff[mt] + ((kbyte + aCb) ^ aXor[mt]));
            uint32_t b[NT16][4];
#pragma unroll
            for (int t = 0; t < NT16; ++t)
                LDSM4(b[t][0], b[t][1], b[t][2], b[t][3],
                      bb + bRowOff[t] + ((kbyte + bCb) ^ bXor[t]));
#pragma unroll
            for (int mt = 0; mt < 4; ++mt)
#pragma unroll
                for (int t = 0; t < NT16; ++t) {
                    MMA16816(acc[mt][2 * t],     a[mt], b[t][0], b[t][1]);
                    MMA16816(acc[mt][2 * t + 1], a[mt], b[t][2], b[t][3]);
                }
        }
    }

    const int rbase = m0 + wm * 64 + (lid >> 2);
    const int cbase = n0 + wn * WN + (lid & 3) * 2;
#pragma unroll
    for (int t = 0; t < 4; ++t) {
        const int col = cbase + t * 8;
        float2 bv = *reinterpret_cast<const float2*>(bias + col);
#pragma unroll
        for (int mt = 0; mt < 4; ++mt) {
            const int r0 = rbase + mt * 16;
            float2 v0 = make_float2(acc[mt][t][0] + bv.x, acc[mt][t][1] + bv.y);
            float2 v1 = make_float2(acc[mt][t][2] + bv.x, acc[mt][t][3] + bv.y);
            *reinterpret_cast<float2*>(Cout + (size_t)r0 * ldc + col) = v0;
            *reinterpret_cast<float2*>(Cout + (size_t)(r0 + 8) * ldc + col) = v1;
        }
    }
}

// ---------------- host launch ----------------
extern "C" void kernel_launch(void* const* d_in, const int* in_sizes, int n_in,
                              void* d_out, int out_size) {
    const float* x    = (const float*)d_in[0];
    const int*   qv   = (const int*)  d_in[1];
    const float* qs   = (const float*)d_in[2];
    const int*   lv   = (const int*)  d_in[3];
    const float* ls   = (const float*)d_in[4];
    const int*   rv   = (const int*)  d_in[5];
    const float* rs   = (const float*)d_in[6];
    const float* bias = (const float*)d_in[7];

    const int DOUT = in_sizes[7];
    const int R    = in_sizes[3] / DOUT;
    const int DIN  = in_sizes[5] / R;
    const int NTOK = in_sizes[0] / DIN;

    __half *xh, *wf, *lh, *rt;
    { void* p; cudaGetSymbolAddress(&p, g_xh); xh = (__half*)p; }
    { void* p; cudaGetSymbolAddress(&p, g_w);  wf = (__half*)p; }
    { void* p; cudaGetSymbolAddress(&p, g_lh); lh = (__half*)p; }
    { void* p; cudaGetSymbolAddress(&p, g_rt); rt = (__half*)p; }

    const int SMEM  = NSTAGE * (BM * 128 + 128 * 128) + 1024;  // GEMM2 97K
    const int SMEMW = 4 * (64 * 128 + 128 * 128) + 1024;       // GEMM_W 97K
    cudaFuncSetAttribute(gemm_hmma,
                         cudaFuncAttributeMaxDynamicSharedMemorySize, SMEM);
    cudaFuncSetAttribute(gemm_w,
                         cudaFuncAttributeMaxDynamicSharedMemorySize, SMEMW);

    // 1) merged prep: l dequant (blocks 0..511) + r dequant-transpose
    const int nbx_rt = DIN / 32;                   // 128
    const int nrt = nbx_rt * (R / 32);             // 1024 transpose tiles
    k_prep_lr<<<512 + nrt, NTHR>>>(
        lv, ls, lh, (size_t)DOUT * R / 4, R / 4, R / GROUPSZ, 512,
        rv, rs, rt, DIN, R, nbx_rt);

    // 2) GEMM_W: W[DOUT, DIN] = lh @ rt^T + dequant(q)   (full-K preload)
    gemm_w<<<dim3(DIN / 128, DOUT / 64), NTHR, SMEMW>>>(lh, rt, wf, qv, qs, DIN);

    // 3) x -> fp16
    k_convert_x<<<2960, NTHR>>>(x, xh, (size_t)NTOK * DIN / 4);

    // 4) GEMM2: out = xh @ W^T + bias   (fp32, K=4096)
    gemm_hmma<<<dim3(DOUT / 128, NTOK / BM), NTHR, SMEM>>>(
        xh, wf, (float*)d_out, bias, DIN, DIN, DIN, DOUT);
}